// round 13
// baseline (speedup 1.0000x reference)
#include <cuda_runtime.h>
#include <cuda_fp16.h>
#include <cstdint>

// Problem constants (fixed shapes for this problem)
#define TT     128
#define NN     50000
#define EE     1600000
#define EE_PAD 1800000     // padded CSR: each node list 4-aligned, len % 4 == 0
#define CIN    16
#define CH     32
#define COUTC  8
#define NB     296         // persistent grid: 148 SMs x 2 blocks of 512 (co-resident)
#define TILES  3125        // NN / 16
#define NPR    1563        // tile pairs per phase sweep
#define APAD   104         // smem row pad (halfs)
#define BPAD   100
#define FULL   0xFFFFFFFFu

// ---------------- scratch (device globals; no runtime allocation) ----------
__device__ int   g_is64;
__device__ int   g_cnt_src[NN];
__device__ int   g_cnt_dst[NN];
__device__ int   g_cursor[NN];
__device__ int   g_off[NN + 1];
__device__ float g_dinv[NN];
__device__ __align__(16) int2   g_csr[EE_PAD];      // {src, w-bits}; pads = {0,0}
__device__ __align__(16) float  g_h[NN * CH];
__device__ float  g_Z[NN * CH];
__device__ __align__(16) __half g_h16[NN * CH];     // fp16 gather mirror of h
__device__ __align__(16) __half g_hR16[NN * CH];    // fp16 gather mirror of h*R
__device__ __align__(16) __half g_X16[(size_t)TT * NN * CIN];   // fp16 X
__device__ __align__(16) __half g_AX16[(size_t)TT * NN * CIN];  // fp16 agg(x_t)

// software grid barrier state (reset each replay by k_count)
__device__ int          g_cnt;
__device__ volatile int g_release;

// half2 load bypassing L1 (cross-SM producer/consumer inside one kernel)
__device__ __forceinline__ __half2 ldcg_h2(const __half* p) {
    unsigned v = __ldcg((const unsigned*)p);
    return *(__half2*)&v;
}

// m16n8k16 fp16 MMA, fp32 accumulate
__device__ __forceinline__ void mma16816(float& c0, float& c1, float& c2, float& c3,
                                         unsigned a0, unsigned a1, unsigned a2, unsigned a3,
                                         unsigned b0, unsigned b1) {
    asm volatile(
        "mma.sync.aligned.m16n8k16.row.col.f32.f16.f16.f32 "
        "{%0,%1,%2,%3}, {%4,%5,%6,%7}, {%8,%9}, {%0,%1,%2,%3};"
        : "+f"(c0), "+f"(c1), "+f"(c2), "+f"(c3)
        : "r"(a0), "r"(a1), "r"(a2), "r"(a3), "r"(b0), "r"(b1));
}

// pair gather, 8-edge unrolled (MLP=8): half-warp owns node n, lane covers
// channels (2cl, 2cl+1). CSR 4-aligned; pad edges {0, w=0} are inert.
__device__ __forceinline__ void gather_pair(const __half* __restrict__ src,
                                            int n, int cl, float& o0, float& o1) {
    int i = g_off[n], end = g_off[n + 1];
    int c2 = 2 * cl;
    float x0 = 0.f, y0 = 0.f, x1 = 0.f, y1 = 0.f;
    for (; i + 8 <= end; i += 8) {
        int4 qa = *(const int4*)&g_csr[i];
        int4 qb = *(const int4*)&g_csr[i + 2];
        int4 qc = *(const int4*)&g_csr[i + 4];
        int4 qd = *(const int4*)&g_csr[i + 6];
        __half2 v0 = ldcg_h2(&src[qa.x * CH + c2]);
        __half2 v1 = ldcg_h2(&src[qa.z * CH + c2]);
        __half2 v2 = ldcg_h2(&src[qb.x * CH + c2]);
        __half2 v3 = ldcg_h2(&src[qb.z * CH + c2]);
        __half2 v4 = ldcg_h2(&src[qc.x * CH + c2]);
        __half2 v5 = ldcg_h2(&src[qc.z * CH + c2]);
        __half2 v6 = ldcg_h2(&src[qd.x * CH + c2]);
        __half2 v7 = ldcg_h2(&src[qd.z * CH + c2]);
        float2 f0 = __half22float2(v0), f1 = __half22float2(v1);
        float2 f2 = __half22float2(v2), f3 = __half22float2(v3);
        float2 f4 = __half22float2(v4), f5 = __half22float2(v5);
        float2 f6 = __half22float2(v6), f7 = __half22float2(v7);
        float w0 = __int_as_float(qa.y), w1 = __int_as_float(qa.w);
        float w2 = __int_as_float(qb.y), w3 = __int_as_float(qb.w);
        float w4 = __int_as_float(qc.y), w5 = __int_as_float(qc.w);
        float w6 = __int_as_float(qd.y), w7 = __int_as_float(qd.w);
        x0 += w0 * f0.x;  y0 += w0 * f0.y;
        x1 += w1 * f1.x;  y1 += w1 * f1.y;
        x0 += w2 * f2.x;  y0 += w2 * f2.y;
        x1 += w3 * f3.x;  y1 += w3 * f3.y;
        x0 += w4 * f4.x;  y0 += w4 * f4.y;
        x1 += w5 * f5.x;  y1 += w5 * f5.y;
        x0 += w6 * f6.x;  y0 += w6 * f6.y;
        x1 += w7 * f7.x;  y1 += w7 * f7.y;
    }
    if (i < end) {   // lists are multiples of 4 -> exactly one 4-edge tail
        int4 qa = *(const int4*)&g_csr[i];
        int4 qb = *(const int4*)&g_csr[i + 2];
        __half2 v0 = ldcg_h2(&src[qa.x * CH + c2]);
        __half2 v1 = ldcg_h2(&src[qa.z * CH + c2]);
        __half2 v2 = ldcg_h2(&src[qb.x * CH + c2]);
        __half2 v3 = ldcg_h2(&src[qb.z * CH + c2]);
        float2 f0 = __half22float2(v0), f1 = __half22float2(v1);
        float2 f2 = __half22float2(v2), f3 = __half22float2(v3);
        float w0 = __int_as_float(qa.y), w1 = __int_as_float(qa.w);
        float w2 = __int_as_float(qb.y), w3 = __int_as_float(qb.w);
        x0 += w0 * f0.x;  y0 += w0 * f0.y;
        x1 += w1 * f1.x;  y1 += w1 * f1.y;
        x0 += w2 * f2.x;  y0 += w2 * f2.y;
        x1 += w3 * f3.x;  y1 += w3 * f3.y;
    }
    o0 = x0 + x1;
    o1 = y0 + y1;
}

// ---------------- launch 0: count + zero + X->fp16 + dtype detect ----------
__global__ void __launch_bounds__(256) k_count(const void* __restrict__ ei,
                                               const float* __restrict__ X, int E) {
    int tid0 = blockIdx.x * blockDim.x + threadIdx.x;
    int stride = gridDim.x * blockDim.x;

    long long v = ((const long long*)ei)[threadIdx.x];
    int bad = (v < 0 || v >= NN) ? 1 : 0;
    int anybad = __syncthreads_or(bad);
    int is64 = anybad ? 0 : 1;
    if (tid0 == 0) { g_is64 = is64; g_cnt = 0; g_release = 0; }

    if (tid0 < E) {
        long long sl, dl;
        if (is64) {
            sl = ((const long long*)ei)[tid0];
            dl = ((const long long*)ei)[(size_t)E + tid0];
        } else {
            sl = ((const int*)ei)[tid0];
            dl = ((const int*)ei)[E + tid0];
        }
        if (sl >= 0 && sl < NN) atomicAdd(&g_cnt_src[(int)sl], 1);
        if (dl >= 0 && dl < NN) atomicAdd(&g_cnt_dst[(int)dl], 1);
    }

    for (int i = tid0; i < NN * CH; i += stride) {
        g_h[i] = 0.f;
        g_h16[i] = __float2half(0.f);
    }
    for (int i = tid0; i < EE_PAD; i += stride) g_csr[i] = make_int2(0, 0);

    const size_t XT4 = (size_t)TT * NN * CIN / 4;
    const float4* X4 = (const float4*)X;
    __half2* X16 = (__half2*)g_X16;
    for (size_t i = tid0; i < XT4; i += stride) {
        float4 x = X4[i];
        X16[i * 2]     = __floats2half2_rn(x.x, x.y);
        X16[i * 2 + 1] = __floats2half2_rn(x.z, x.w);
    }
}

// ---------------- launch 1: dinv + PADDED exclusive scan (single block) ----
__global__ void __launch_bounds__(1024) k_scan() {
    __shared__ int s[1024];
    __shared__ int carry_s;
    int tid = threadIdx.x;
    for (int n = tid; n < NN; n += 1024) {
        int dsrc = g_cnt_src[n];
        g_dinv[n] = (dsrc > 0) ? rsqrtf((float)dsrc) : 0.f;
    }
    if (tid == 0) carry_s = 0;
    __syncthreads();
    for (int base = 0; base < NN; base += 1024) {
        int i = base + tid;
        int v = (i < NN) ? ((g_cnt_dst[i] + 3) & ~3) : 0;
        s[tid] = v;
        __syncthreads();
        for (int off = 1; off < 1024; off <<= 1) {
            int x = (tid >= off) ? s[tid - off] : 0;
            __syncthreads();
            s[tid] += x;
            __syncthreads();
        }
        if (i < NN) g_off[i] = carry_s + s[tid] - v;
        __syncthreads();
        if (tid == 0) carry_s += s[1023];
        __syncthreads();
    }
    if (tid == 0) g_off[NN] = carry_s;
}

// ---------------- launch 2: fill CSR ----------------
__global__ void k_fill(const void* __restrict__ ei, int E) {
    int i = blockIdx.x * blockDim.x + threadIdx.x;
    if (i >= E) return;
    long long sl, dl;
    if (g_is64) {
        sl = ((const long long*)ei)[i];
        dl = ((const long long*)ei)[(size_t)E + i];
    } else {
        sl = ((const int*)ei)[i];
        dl = ((const int*)ei)[E + i];
    }
    if (sl < 0 || sl >= NN || dl < 0 || dl >= NN) return;
    int s = (int)sl, d = (int)dl;
    int pos = g_off[d] + atomicAdd(&g_cursor[d], 1);
    g_csr[pos] = make_int2(s, __float_as_int(-g_dinv[s] * g_dinv[d]));
}

// ---------------- launch 3: persistent kernel (AX prologue + recurrence) ---
// 296 blocks x 512 thr (16 warps = two 8-warp halves), co-resident.
// Each block iteration: TWO 16-node tiles (one per half).
__global__ void __launch_bounds__(512, 2) k_gru(
    const float* __restrict__ Wxz, const float* __restrict__ bxz,
    const float* __restrict__ Whz, const float* __restrict__ bhz,
    const float* __restrict__ Wxr, const float* __restrict__ bxr,
    const float* __restrict__ Whr, const float* __restrict__ bhr,
    const float* __restrict__ Wxh, const float* __restrict__ bxh,
    const float* __restrict__ Whh, const float* __restrict__ bhh,
    const float* __restrict__ fcw, const float* __restrict__ fcb,
    float* __restrict__ out)
{
    __shared__ __align__(16) __half sA[2][16][APAD];     // operand tiles (per half)
    __shared__ __align__(16) __half sBAh[64][APAD];      // phase-A weights hi
    __shared__ __align__(16) __half sBAl[64][APAD];      // phase-A weights lo
    __shared__ __align__(16) __half sBBh[32][BPAD];      // phase-B weights hi
    __shared__ __align__(16) __half sBBl[32][BPAD];      // phase-B weights lo
    __shared__ __align__(16) float  sZT[2][16][68];      // fp32 acc/exchange tiles
    __shared__ float s_bz[CH], s_br[CH], s_bh[CH];
    __shared__ float s_fcw[CH * COUTC], s_fcb[COUTC];

    int tid = threadIdx.x;
    int lane = tid & 31, wid = tid >> 5;

    // ---- stage weights: B row k maps A cols: [x(0..15)|ax(16..31)|h(32..63)|a(64..95)]
    for (int idx = tid; idx < 64 * 96; idx += 512) {
        int j = idx / 96, k = idx % 96;
        int jj = (j < 32) ? j : j - 32;
        const float* Wx = (j < 32) ? Wxz : Wxr;
        const float* Wh = (j < 32) ? Whz : Whr;
        float w;
        if      (k < 16) w = Wx[k * CH + jj];
        else if (k < 32) w = Wx[CIN * CH + (k - 16) * CH + jj];
        else if (k < 64) w = Wh[(k - 32) * CH + jj];
        else             w = Wh[CH * CH + (k - 64) * CH + jj];
        __half hi = __float2half_rn(w);
        sBAh[j][k] = hi;
        sBAl[j][k] = __float2half_rn(w - __half2float(hi));
    }
    for (int idx = tid; idx < 32 * 96; idx += 512) {
        int j = idx / 96, k = idx % 96;
        float w;
        if      (k < 16) w = Wxh[k * CH + j];
        else if (k < 32) w = Wxh[CIN * CH + (k - 16) * CH + j];
        else if (k < 64) w = Whh[(k - 32) * CH + j];
        else             w = Whh[CH * CH + (k - 64) * CH + j];
        __half hi = __float2half_rn(w);
        sBBh[j][k] = hi;
        sBBl[j][k] = __float2half_rn(w - __half2float(hi));
    }
    for (int i = tid; i < CH * COUTC; i += 512) s_fcw[i] = fcw[i];
    if (tid < CH) {
        s_bz[tid] = bxz[tid] + bhz[tid];
        s_br[tid] = bxr[tid] + bhr[tid];
        s_bh[tid] = bxh[tid] + bhh[tid];
    }
    if (tid < COUTC) s_fcb[tid] = fcb[tid];
    __syncthreads();

    // ---- prologue: counter rezero + AX precompute (warp = node x 4 timesteps)
    for (int i = blockIdx.x * 512 + tid; i < NN; i += NB * 512) {
        g_cnt_src[i] = 0; g_cnt_dst[i] = 0; g_cursor[i] = 0;
    }
    {
        int tsub = lane >> 3;          // 0..3 timestep-in-quad
        int cl8  = lane & 7;           // channel pair (2cl8, 2cl8+1) of 16
        int gwarp = blockIdx.x * 16 + wid;
        for (int u = gwarp; u < NN * (TT / 4); u += NB * 16) {
            int tq = u / NN, n = u - tq * NN;
            int t = tq * 4 + tsub;
            const __half* Xt = g_X16 + (size_t)t * NN * CIN;
            int beg = g_off[n], end = g_off[n + 1];
            int c2 = 2 * cl8;
            float x0 = 0.f, y0 = 0.f, x1 = 0.f, y1 = 0.f;
            for (int i = beg; i < end; i += 4) {
                int4 qa = *(const int4*)&g_csr[i];
                int4 qb = *(const int4*)&g_csr[i + 2];
                float2 f0 = __half22float2(*(const __half2*)&Xt[qa.x * CIN + c2]);
                float2 f1 = __half22float2(*(const __half2*)&Xt[qa.z * CIN + c2]);
                float2 f2 = __half22float2(*(const __half2*)&Xt[qb.x * CIN + c2]);
                float2 f3 = __half22float2(*(const __half2*)&Xt[qb.z * CIN + c2]);
                float w0 = __int_as_float(qa.y), w1 = __int_as_float(qa.w);
                float w2 = __int_as_float(qb.y), w3 = __int_as_float(qb.w);
                x0 += w0 * f0.x;  y0 += w0 * f0.y;
                x1 += w1 * f1.x;  y1 += w1 * f1.y;
                x0 += w2 * f2.x;  y0 += w2 * f2.y;
                x1 += w3 * f3.x;  y1 += w3 * f3.y;
            }
            *(__half2*)&g_AX16[((size_t)t * NN + n) * CIN + c2] =
                __floats2half2_rn(x0 + x1, y0 + y1);
        }
    }

    int gen = 1;   // AX barrier
    __syncthreads();
    if (tid == 0) {
        __threadfence();
        if (atomicAdd(&g_cnt, 1) == NB - 1) {
            g_cnt = 0;
            __threadfence();
            g_release = gen;
        } else {
            while (g_release < gen) { }
        }
    }
    __syncthreads();

    int half = wid >> 3, wl = wid & 7;      // half-block / warp-in-half
    int g = lane >> 2, tq4 = lane & 3;      // mma group / thread-in-group
    int r0 = 2 * wl, r1 = r0 + 1;           // tile rows owned by this warp
    int hw = lane >> 4, cl = lane & 15;     // pair-gather half / channel-pair
    int c2 = 2 * cl;
    int htid = tid & 255;                   // thread id within half

    for (int t = 0; t < TT; t++) {
        const __half* Xt  = g_X16  + (size_t)t * NN * CIN;
        const __half* AXt = g_AX16 + (size_t)t * NN * CIN;

        // ================= phase A: z, r, h*R =================
        for (int pr = blockIdx.x; pr < NPR; pr += NB) {
            int tile = 2 * pr + half;
            bool valid = tile < TILES;
            int n0 = tile * 16;
            if (valid) {
                int n = n0 + (hw ? r1 : r0);
                int r = hw ? r1 : r0;
                __half2 xv = (cl < 8) ? *(const __half2*)&Xt[n * CIN + c2]
                                      : *(const __half2*)&AXt[n * CIN + (c2 - 16)];
                *(__half2*)&sA[half][r][c2] = xv;
                *(__half2*)&sA[half][r][32 + c2] = *(const __half2*)&g_h16[n * CH + c2];
                float e0, e1;
                gather_pair(g_h16, n, cl, e0, e1);
                *(__half2*)&sA[half][r][64 + c2] = __floats2half2_rn(e0, e1);
            }
            __syncthreads();

            // mma: warp owns output cols 8*wl..8*wl+7 of [z(0..31)|r(32..63)]
            float c0 = 0.f, c1 = 0.f, cc2 = 0.f, c3 = 0.f;
            int j = 8 * wl + g;
#pragma unroll
            for (int kt = 0; kt < 6; kt++) {
                int kc = kt * 16 + 2 * tq4;
                unsigned a0 = *(const unsigned*)&sA[half][g][kc];
                unsigned a1 = *(const unsigned*)&sA[half][g + 8][kc];
                unsigned a2 = *(const unsigned*)&sA[half][g][kc + 8];
                unsigned a3 = *(const unsigned*)&sA[half][g + 8][kc + 8];
                unsigned b0 = *(const unsigned*)&sBAh[j][kc];
                unsigned b1 = *(const unsigned*)&sBAh[j][kc + 8];
                mma16816(c0, c1, cc2, c3, a0, a1, a2, a3, b0, b1);
                if (kt >= 2) {
                    unsigned l0 = *(const unsigned*)&sBAl[j][kc];
                    unsigned l1 = *(const unsigned*)&sBAl[j][kc + 8];
                    mma16816(c0, c1, cc2, c3, a0, a1, a2, a3, l0, l1);
                }
            }
            int jc = 8 * wl + 2 * tq4;
            *(float2*)&sZT[half][g][jc]     = make_float2(c0, c1);
            *(float2*)&sZT[half][g + 8][jc] = make_float2(cc2, c3);
            __syncthreads();

            if (valid) {
#pragma unroll
                for (int q = 0; q < 2; q++) {
                    int it = htid + q * 256;
                    int nn = it >> 5, c = it & 31;
                    int gn = n0 + nn;
                    float z = 1.f / (1.f + __expf(-(sZT[half][nn][c] + s_bz[c])));
                    float rr = 1.f / (1.f + __expf(-(sZT[half][nn][32 + c] + s_br[c])));
                    float hr = g_h[gn * CH + c] * rr;
                    g_Z[gn * CH + c] = z;
                    g_hR16[gn * CH + c] = __float2half(hr);
                }
            }
            __syncthreads();
        }

        // ---- grid barrier (hR16 published) ----
        gen++;
        __syncthreads();
        if (tid == 0) {
            __threadfence();
            if (atomicAdd(&g_cnt, 1) == NB - 1) {
                g_cnt = 0;
                __threadfence();
                g_release = gen;
            } else {
                while (g_release < gen) { }
            }
        }
        __syncthreads();

        // ================= phase B: candidate + blend + fc =================
        for (int pr = blockIdx.x; pr < NPR; pr += NB) {
            int tile = 2 * pr + half;
            bool valid = tile < TILES;
            int n0 = tile * 16;
            if (valid) {
                int n = n0 + (hw ? r1 : r0);
                int r = hw ? r1 : r0;
                __half2 xv = (cl < 8) ? *(const __half2*)&Xt[n * CIN + c2]
                                      : *(const __half2*)&AXt[n * CIN + (c2 - 16)];
                *(__half2*)&sA[half][r][c2] = xv;
                *(__half2*)&sA[half][r][32 + c2] = *(const __half2*)&g_hR16[n * CH + c2];
                float e0, e1;
                gather_pair(g_hR16, n, cl, e0, e1);
                *(__half2*)&sA[half][r][64 + c2] = __floats2half2_rn(e0, e1);
            }
            __syncthreads();

            // warps wl 0..3: hi-weights (all kt); wl 4..7: lo-weights (kt>=2)
            float c0 = 0.f, c1 = 0.f, cc2 = 0.f, c3 = 0.f;
            int wsub = wl & 3;
            int j = 8 * wsub + g;
            if (wl < 4) {
#pragma unroll
                for (int kt = 0; kt < 6; kt++) {
                    int kc = kt * 16 + 2 * tq4;
                    unsigned a0 = *(const unsigned*)&sA[half][g][kc];
                    unsigned a1 = *(const unsigned*)&sA[half][g + 8][kc];
                    unsigned a2 = *(const unsigned*)&sA[half][g][kc + 8];
                    unsigned a3 = *(const unsigned*)&sA[half][g + 8][kc + 8];
                    unsigned b0 = *(const unsigned*)&sBBh[j][kc];
                    unsigned b1 = *(const unsigned*)&sBBh[j][kc + 8];
                    mma16816(c0, c1, cc2, c3, a0, a1, a2, a3, b0, b1);
                }
            } else {
#pragma unroll
                for (int kt = 2; kt < 6; kt++) {
                    int kc = kt * 16 + 2 * tq4;
                    unsigned a0 = *(const unsigned*)&sA[half][g][kc];
                    unsigned a1 = *(const unsigned*)&sA[half][g + 8][kc];
                    unsigned a2 = *(const unsigned*)&sA[half][g][kc + 8];
                    unsigned a3 = *(const unsigned*)&sA[half][g + 8][kc + 8];
                    unsigned b0 = *(const unsigned*)&sBBl[j][kc];
                    unsigned b1 = *(const unsigned*)&sBBl[j][kc + 8];
                    mma16816(c0, c1, cc2, c3, a0, a1, a2, a3, b0, b1);
                }
            }
            int jc = ((wl < 4) ? 0 : 32) + 8 * wsub + 2 * tq4;
            *(float2*)&sZT[half][g][jc]     = make_float2(c0, c1);
            *(float2*)&sZT[half][g + 8][jc] = make_float2(cc2, c3);
            __syncthreads();

            float hn[2];
            if (valid) {
#pragma unroll
                for (int q = 0; q < 2; q++) {
                    int it = htid + q * 256;
                    int nn = it >> 5, c = it & 31;
                    int gn = n0 + nn;
                    float ct = sZT[half][nn][c] + sZT[half][nn][32 + c] + s_bh[c];
                    float z = g_Z[gn * CH + c];
                    float h = g_h[gn * CH + c];
                    float v = z * h + (1.f - z) * tanhf(ct);
                    hn[q] = v;
                    g_h[gn * CH + c] = v;
                    g_h16[gn * CH + c] = __float2half(v);
                }
            }
            __syncthreads();
            if (valid) {
#pragma unroll
                for (int q = 0; q < 2; q++) {
                    int it = htid + q * 256;
                    sZT[half][it >> 5][it & 31] = hn[q];
                }
            }
            __syncthreads();
            if (valid && htid < 128) {
                int nn = htid >> 3, jj = htid & 7;
                float acc = s_fcb[jj];
#pragma unroll
                for (int c = 0; c < CH; c++) acc += sZT[half][nn][c] * s_fcw[c * COUTC + jj];
                out[((size_t)t * NN + n0 + nn) * COUTC + jj] = acc;
            }
            __syncthreads();
        }

        // ---- grid barrier (h published for next step) ----
        gen++;
        __syncthreads();
        if (tid == 0) {
            __threadfence();
            if (atomicAdd(&g_cnt, 1) == NB - 1) {
                g_cnt = 0;
                __threadfence();
                g_release = gen;
            } else {
                while (g_release < gen) { }
            }
        }
        __syncthreads();
    }
}

// ---------------- launch ----------------
extern "C" void kernel_launch(void* const* d_in, const int* in_sizes, int n_in,
                              void* d_out, int out_size) {
    const float* X   = (const float*)d_in[0];
    const void*  ei  = d_in[1];
    const float* Wxz = (const float*)d_in[2];
    const float* bxz = (const float*)d_in[3];
    const float* Whz = (const float*)d_in[4];
    const float* bhz = (const float*)d_in[5];
    const float* Wxr = (const float*)d_in[6];
    const float* bxr = (const float*)d_in[7];
    const float* Whr = (const float*)d_in[8];
    const float* bhr = (const float*)d_in[9];
    const float* Wxh = (const float*)d_in[10];
    const float* bxh = (const float*)d_in[11];
    const float* Whh = (const float*)d_in[12];
    const float* bhh = (const float*)d_in[13];
    const float* fcw = (const float*)d_in[14];
    const float* fcb = (const float*)d_in[15];
    float* out = (float*)d_out;

    int E = in_sizes[1] / 2;

    // preprocess: count(0), scan(1), fill(2) -> k_gru is launch idx 3
    k_count<<<(E + 255) / 256, 256>>>(ei, X, E);
    k_scan<<<1, 1024>>>();
    k_fill<<<(E + 255) / 256, 256>>>(ei, E);

    // persistent: AX prologue + all 128 recurrence steps in ONE launch
    k_gru<<<NB, 512>>>(Wxz, bxz, Whz, bhz, Wxr, bxr, Whr, bhr,
                       Wxh, bxh, Whh, bhh, fcw, fcb, out);
}

// round 14
// speedup vs baseline: 1.0254x; 1.0254x over previous
#include <cuda_runtime.h>
#include <cuda_fp16.h>
#include <cstdint>

// Problem constants (fixed shapes for this problem)
#define TT     128
#define NN     50000
#define EE     1600000
#define EE_PAD 1800000     // padded CSR: each node list 4-aligned, len % 4 == 0
#define CIN    16
#define CH     32
#define COUTC  8
#define NB     592         // persistent grid: 148 SMs x 4 blocks (co-resident)
#define TILES  3125        // NN / 16
#define FULL   0xFFFFFFFFu

// ---------------- scratch (device globals; no runtime allocation) ----------
__device__ int   g_is64;
__device__ int   g_cnt_src[NN];
__device__ int   g_cnt_dst[NN];
__device__ int   g_cursor[NN];
__device__ int   g_off[NN + 1];
__device__ float g_dinv[NN];
__device__ __align__(16) int2   g_csr[EE_PAD];      // {src, w-bits}; pads = {0,0}
__device__ __align__(16) float  g_h[NN * CH];
__device__ float  g_Z[NN * CH];
__device__ __align__(16) __half g_h16[NN * CH];     // fp16 gather mirror of h
__device__ __align__(16) __half g_hR16[NN * CH];    // fp16 gather mirror of h*R
__device__ __align__(16) __half g_X16[(size_t)TT * NN * CIN];   // fp16 X
__device__ __align__(16) __half g_AX16[(size_t)TT * NN * CIN];  // fp16 agg(x_t)

// software grid barrier state (reset each replay by k_count)
__device__ int          g_cnt;
__device__ volatile int g_release;

// permuted ldmatrix-style index: operand half k of row `r` lives at
//   [kt = k>>4][r][quad tq' = (k&7)>>1][hi8 = (k&15)>=8 ? +2 : 0][k&1]
// so a lane's (a0,a2) or (b0,b1) fragment pair is ONE aligned uint2 (LDS.64).
__device__ __forceinline__ int ap_idx(int r, int k, int nrows) {
    return (((k >> 4) * nrows + r) << 4)
         + (((k & 7) >> 1) << 2)
         + (((k & 15) >= 8) ? 2 : 0)
         + (k & 1);
}

// half2 load bypassing L1 (cross-SM producer/consumer inside one kernel)
__device__ __forceinline__ __half2 ldcg_h2(const __half* p) {
    unsigned v = __ldcg((const unsigned*)p);
    return *(__half2*)&v;
}

// m16n8k16 fp16 MMA, fp32 accumulate
__device__ __forceinline__ void mma16816(float& c0, float& c1, float& c2, float& c3,
                                         unsigned a0, unsigned a1, unsigned a2, unsigned a3,
                                         unsigned b0, unsigned b1) {
    asm volatile(
        "mma.sync.aligned.m16n8k16.row.col.f32.f16.f16.f32 "
        "{%0,%1,%2,%3}, {%4,%5,%6,%7}, {%8,%9}, {%0,%1,%2,%3};"
        : "+f"(c0), "+f"(c1), "+f"(c2), "+f"(c3)
        : "r"(a0), "r"(a1), "r"(a2), "r"(a3), "r"(b0), "r"(b1));
}

// pair gather (R12-proven): half-warp owns node n, lane covers channels
// (2cl, 2cl+1). CSR 4-aligned; pad edges {0, w=0} are numerically inert.
__device__ __forceinline__ void gather_pair(const __half* __restrict__ src,
                                            int n, int cl, float& o0, float& o1) {
    int beg = g_off[n], end = g_off[n + 1];
    int c2 = 2 * cl;
    float x0 = 0.f, y0 = 0.f, x1 = 0.f, y1 = 0.f;
    for (int i = beg; i < end; i += 4) {
        int4 qa = *(const int4*)&g_csr[i];
        int4 qb = *(const int4*)&g_csr[i + 2];
        __half2 v0 = ldcg_h2(&src[qa.x * CH + c2]);
        __half2 v1 = ldcg_h2(&src[qa.z * CH + c2]);
        __half2 v2 = ldcg_h2(&src[qb.x * CH + c2]);
        __half2 v3 = ldcg_h2(&src[qb.z * CH + c2]);
        float w0 = __int_as_float(qa.y), w1 = __int_as_float(qa.w);
        float w2 = __int_as_float(qb.y), w3 = __int_as_float(qb.w);
        float2 f0 = __half22float2(v0), f1 = __half22float2(v1);
        float2 f2 = __half22float2(v2), f3 = __half22float2(v3);
        x0 += w0 * f0.x;  y0 += w0 * f0.y;
        x1 += w1 * f1.x;  y1 += w1 * f1.y;
        x0 += w2 * f2.x;  y0 += w2 * f2.y;
        x1 += w3 * f3.x;  y1 += w3 * f3.y;
    }
    o0 = x0 + x1;
    o1 = y0 + y1;
}

// ---------------- launch 0: count + zero + X->fp16 + dtype detect ----------
__global__ void __launch_bounds__(256) k_count(const void* __restrict__ ei,
                                               const float* __restrict__ X, int E) {
    int tid0 = blockIdx.x * blockDim.x + threadIdx.x;
    int stride = gridDim.x * blockDim.x;

    long long v = ((const long long*)ei)[threadIdx.x];
    int bad = (v < 0 || v >= NN) ? 1 : 0;
    int anybad = __syncthreads_or(bad);
    int is64 = anybad ? 0 : 1;
    if (tid0 == 0) { g_is64 = is64; g_cnt = 0; g_release = 0; }

    if (tid0 < E) {
        long long sl, dl;
        if (is64) {
            sl = ((const long long*)ei)[tid0];
            dl = ((const long long*)ei)[(size_t)E + tid0];
        } else {
            sl = ((const int*)ei)[tid0];
            dl = ((const int*)ei)[E + tid0];
        }
        if (sl >= 0 && sl < NN) atomicAdd(&g_cnt_src[(int)sl], 1);
        if (dl >= 0 && dl < NN) atomicAdd(&g_cnt_dst[(int)dl], 1);
    }

    for (int i = tid0; i < NN * CH; i += stride) {
        g_h[i] = 0.f;
        g_h16[i] = __float2half(0.f);
    }
    for (int i = tid0; i < EE_PAD; i += stride) g_csr[i] = make_int2(0, 0);

    const size_t XT4 = (size_t)TT * NN * CIN / 4;
    const float4* X4 = (const float4*)X;
    __half2* X16 = (__half2*)g_X16;
    for (size_t i = tid0; i < XT4; i += stride) {
        float4 x = X4[i];
        X16[i * 2]     = __floats2half2_rn(x.x, x.y);
        X16[i * 2 + 1] = __floats2half2_rn(x.z, x.w);
    }
}

// ---------------- launch 1: dinv + PADDED exclusive scan (single block) ----
__global__ void __launch_bounds__(1024) k_scan() {
    __shared__ int s[1024];
    __shared__ int carry_s;
    int tid = threadIdx.x;
    for (int n = tid; n < NN; n += 1024) {
        int dsrc = g_cnt_src[n];
        g_dinv[n] = (dsrc > 0) ? rsqrtf((float)dsrc) : 0.f;
    }
    if (tid == 0) carry_s = 0;
    __syncthreads();
    for (int base = 0; base < NN; base += 1024) {
        int i = base + tid;
        int v = (i < NN) ? ((g_cnt_dst[i] + 3) & ~3) : 0;
        s[tid] = v;
        __syncthreads();
        for (int off = 1; off < 1024; off <<= 1) {
            int x = (tid >= off) ? s[tid - off] : 0;
            __syncthreads();
            s[tid] += x;
            __syncthreads();
        }
        if (i < NN) g_off[i] = carry_s + s[tid] - v;
        __syncthreads();
        if (tid == 0) carry_s += s[1023];
        __syncthreads();
    }
    if (tid == 0) g_off[NN] = carry_s;
}

// ---------------- launch 2: fill CSR ----------------
__global__ void k_fill(const void* __restrict__ ei, int E) {
    int i = blockIdx.x * blockDim.x + threadIdx.x;
    if (i >= E) return;
    long long sl, dl;
    if (g_is64) {
        sl = ((const long long*)ei)[i];
        dl = ((const long long*)ei)[(size_t)E + i];
    } else {
        sl = ((const int*)ei)[i];
        dl = ((const int*)ei)[E + i];
    }
    if (sl < 0 || sl >= NN || dl < 0 || dl >= NN) return;
    int s = (int)sl, d = (int)dl;
    int pos = g_off[d] + atomicAdd(&g_cursor[d], 1);
    g_csr[pos] = make_int2(s, __float_as_int(-g_dinv[s] * g_dinv[d]));
}

// ---------------- launch 3: persistent kernel (AX prologue + recurrence) ---
// 592 blocks x 256 thr (8 warps), co-resident. Block processes 16-node tiles.
// Dense per tile: A[16x96]=[x|ax|h|agg] fp16 @ B[96x64] split-fp16 weights,
// ALL operands in ldmatrix-style permuted smem (LDS.64 frag pairs, 2 wf each).
__global__ void __launch_bounds__(256, 4) k_gru(
    const float* __restrict__ Wxz, const float* __restrict__ bxz,
    const float* __restrict__ Whz, const float* __restrict__ bhz,
    const float* __restrict__ Wxr, const float* __restrict__ bxr,
    const float* __restrict__ Whr, const float* __restrict__ bhr,
    const float* __restrict__ Wxh, const float* __restrict__ bxh,
    const float* __restrict__ Whh, const float* __restrict__ bhh,
    const float* __restrict__ fcw, const float* __restrict__ fcb,
    float* __restrict__ out)
{
    __shared__ __align__(16) __half sAp  [6 * 16 * 16];   // operand tile, permuted (3KB)
    __shared__ __align__(16) __half sBAph[6 * 64 * 16];   // phase-A weights hi (12KB)
    __shared__ __align__(16) __half sBApl[6 * 64 * 16];   // phase-A weights lo (12KB)
    __shared__ __align__(16) __half sBBph[6 * 32 * 16];   // phase-B weights hi (6KB)
    __shared__ __align__(16) __half sBBpl[6 * 32 * 16];   // phase-B weights lo (6KB)
    __shared__ __align__(16) float  sZT[16][68];          // fp32 acc/exchange (4.3KB)
    __shared__ float s_bz[CH], s_br[CH], s_bh[CH];
    __shared__ float s_fcw[CH * COUTC], s_fcb[COUTC];

    int tid = threadIdx.x;
    int lane = tid & 31, wid = tid >> 5;

    // ---- stage weights (permuted): B row k maps A cols [x|ax|h|agg] ----
    for (int idx = tid; idx < 64 * 96; idx += 256) {
        int j = idx / 96, k = idx % 96;
        int jj = (j < 32) ? j : j - 32;
        const float* Wx = (j < 32) ? Wxz : Wxr;
        const float* Wh = (j < 32) ? Whz : Whr;
        float w;
        if      (k < 16) w = Wx[k * CH + jj];
        else if (k < 32) w = Wx[CIN * CH + (k - 16) * CH + jj];
        else if (k < 64) w = Wh[(k - 32) * CH + jj];
        else             w = Wh[CH * CH + (k - 64) * CH + jj];
        __half hi = __float2half_rn(w);
        int pi = ap_idx(j, k, 64);
        sBAph[pi] = hi;
        sBApl[pi] = __float2half_rn(w - __half2float(hi));
    }
    for (int idx = tid; idx < 32 * 96; idx += 256) {
        int j = idx / 96, k = idx % 96;
        float w;
        if      (k < 16) w = Wxh[k * CH + j];
        else if (k < 32) w = Wxh[CIN * CH + (k - 16) * CH + j];
        else if (k < 64) w = Whh[(k - 32) * CH + j];
        else             w = Whh[CH * CH + (k - 64) * CH + j];
        __half hi = __float2half_rn(w);
        int pi = ap_idx(j, k, 32);
        sBBph[pi] = hi;
        sBBpl[pi] = __float2half_rn(w - __half2float(hi));
    }
    for (int i = tid; i < CH * COUTC; i += 256) s_fcw[i] = fcw[i];
    if (tid < CH) {
        s_bz[tid] = bxz[tid] + bhz[tid];
        s_br[tid] = bxr[tid] + bhr[tid];
        s_bh[tid] = bxh[tid] + bhh[tid];
    }
    if (tid < COUTC) s_fcb[tid] = fcb[tid];
    __syncthreads();

    // ---- prologue: counter rezero + AX precompute (warp = node x 4 timesteps)
    for (int i = blockIdx.x * 256 + tid; i < NN; i += NB * 256) {
        g_cnt_src[i] = 0; g_cnt_dst[i] = 0; g_cursor[i] = 0;
    }
    {
        int tsub = lane >> 3;          // 0..3 timestep-in-quad
        int cl8  = lane & 7;           // channel pair (2cl8, 2cl8+1) of 16
        int gwarp = blockIdx.x * 8 + wid;
        for (int u = gwarp; u < NN * (TT / 4); u += NB * 8) {
            int tq = u / NN, n = u - tq * NN;
            int t = tq * 4 + tsub;
            const __half* Xt = g_X16 + (size_t)t * NN * CIN;
            int beg = g_off[n], end = g_off[n + 1];
            int c2 = 2 * cl8;
            float x0 = 0.f, y0 = 0.f, x1 = 0.f, y1 = 0.f;
            for (int i = beg; i < end; i += 4) {
                int4 qa = *(const int4*)&g_csr[i];
                int4 qb = *(const int4*)&g_csr[i + 2];
                float2 f0 = __half22float2(*(const __half2*)&Xt[qa.x * CIN + c2]);
                float2 f1 = __half22float2(*(const __half2*)&Xt[qa.z * CIN + c2]);
                float2 f2 = __half22float2(*(const __half2*)&Xt[qb.x * CIN + c2]);
                float2 f3 = __half22float2(*(const __half2*)&Xt[qb.z * CIN + c2]);
                float w0 = __int_as_float(qa.y), w1 = __int_as_float(qa.w);
                float w2 = __int_as_float(qb.y), w3 = __int_as_float(qb.w);
                x0 += w0 * f0.x;  y0 += w0 * f0.y;
                x1 += w1 * f1.x;  y1 += w1 * f1.y;
                x0 += w2 * f2.x;  y0 += w2 * f2.y;
                x1 += w3 * f3.x;  y1 += w3 * f3.y;
            }
            *(__half2*)&g_AX16[((size_t)t * NN + n) * CIN + c2] =
                __floats2half2_rn(x0 + x1, y0 + y1);
        }
    }

    int gen = 1;   // AX barrier
    __syncthreads();
    if (tid == 0) {
        __threadfence();
        if (atomicAdd(&g_cnt, 1) == NB - 1) {
            g_cnt = 0;
            __threadfence();
            g_release = gen;
        } else {
            while (g_release < gen) { }
        }
    }
    __syncthreads();

    int g = lane >> 2, tq4 = lane & 3;      // mma group / thread-in-group
    int r0 = 2 * wid, r1 = r0 + 1;          // tile rows owned by this warp
    int hw = lane >> 4, cl = lane & 15;     // pair-gather half / channel-pair
    int c2 = 2 * cl;

    for (int t = 0; t < TT; t++) {
        const __half* Xt  = g_X16  + (size_t)t * NN * CIN;
        const __half* AXt = g_AX16 + (size_t)t * NN * CIN;

        // ================= phase A: z, r, h*R =================
        for (int tile = blockIdx.x; tile < TILES; tile += NB) {
            int n0 = tile * 16;
            int nA = n0 + r0, nB = n0 + r1;
            int n = hw ? nB : nA;
            int r = hw ? r1 : r0;
            // x|ax (operand cols 0..31)
            __half2 xv = (cl < 8) ? *(const __half2*)&Xt[n * CIN + c2]
                                  : *(const __half2*)&AXt[n * CIN + (c2 - 16)];
            *(__half2*)&sAp[ap_idx(r, c2, 16)] = xv;
            // h (cols 32..63) — own nodes, written by this block last step
            *(__half2*)&sAp[ap_idx(r, 32 + c2, 16)] = *(const __half2*)&g_h16[n * CH + c2];
            // gather agg(h) (cols 64..95)
            float e0, e1;
            gather_pair(g_h16, n, cl, e0, e1);
            *(__half2*)&sAp[ap_idx(r, 64 + c2, 16)] = __floats2half2_rn(e0, e1);
            __syncthreads();

            // mma: warp owns output cols 8*wid..8*wid+7 of [z(0..31)|r(32..63)]
            float c0 = 0.f, c1 = 0.f, cc2 = 0.f, c3 = 0.f;
            int j = 8 * wid + g;
#pragma unroll
            for (int kt = 0; kt < 6; kt++) {
                uint2 a02 = *(const uint2*)&sAp[((kt * 16 + g) << 4) + tq4 * 4];
                uint2 a13 = *(const uint2*)&sAp[((kt * 16 + g + 8) << 4) + tq4 * 4];
                uint2 bb  = *(const uint2*)&sBAph[((kt * 64 + j) << 4) + tq4 * 4];
                mma16816(c0, c1, cc2, c3, a02.x, a13.x, a02.y, a13.y, bb.x, bb.y);
                if (kt >= 2) {   // lo-split only for recurrent (h/agg) weights
                    uint2 ll = *(const uint2*)&sBApl[((kt * 64 + j) << 4) + tq4 * 4];
                    mma16816(c0, c1, cc2, c3, a02.x, a13.x, a02.y, a13.y, ll.x, ll.y);
                }
            }
            int jc = 8 * wid + 2 * tq4;
            *(float2*)&sZT[g][jc]     = make_float2(c0, c1);
            *(float2*)&sZT[g + 8][jc] = make_float2(cc2, c3);
            __syncthreads();

            // epilogue: 512 (node,channel) items
#pragma unroll
            for (int it = tid; it < 512; it += 256) {
                int nn = it >> 5, c = it & 31;
                int gn = n0 + nn;
                float z = 1.f / (1.f + __expf(-(sZT[nn][c] + s_bz[c])));
                float rr = 1.f / (1.f + __expf(-(sZT[nn][32 + c] + s_br[c])));
                float hr = g_h[gn * CH + c] * rr;
                g_Z[gn * CH + c] = z;
                g_hR16[gn * CH + c] = __float2half(hr);
            }
            __syncthreads();
        }

        // ---- grid barrier (hR16 published) ----
        gen++;
        __syncthreads();
        if (tid == 0) {
            __threadfence();
            if (atomicAdd(&g_cnt, 1) == NB - 1) {
                g_cnt = 0;
                __threadfence();
                g_release = gen;
            } else {
                while (g_release < gen) { }
            }
        }
        __syncthreads();

        // ================= phase B: candidate + blend + fc =================
        for (int tile = blockIdx.x; tile < TILES; tile += NB) {
            int n0 = tile * 16;
            int nA = n0 + r0, nB = n0 + r1;
            int n = hw ? nB : nA;
            int r = hw ? r1 : r0;
            __half2 xv = (cl < 8) ? *(const __half2*)&Xt[n * CIN + c2]
                                  : *(const __half2*)&AXt[n * CIN + (c2 - 16)];
            *(__half2*)&sAp[ap_idx(r, c2, 16)] = xv;
            *(__half2*)&sAp[ap_idx(r, 32 + c2, 16)] = *(const __half2*)&g_hR16[n * CH + c2];
            float e0, e1;
            gather_pair(g_hR16, n, cl, e0, e1);
            *(__half2*)&sAp[ap_idx(r, 64 + c2, 16)] = __floats2half2_rn(e0, e1);
            __syncthreads();

            // warps 0..3: hi-weights (all kt); warps 4..7: lo-weights (kt>=2)
            float c0 = 0.f, c1 = 0.f, cc2 = 0.f, c3 = 0.f;
            int wsub = wid & 3;
            int j = 8 * wsub + g;
            if (wid < 4) {
#pragma unroll
                for (int kt = 0; kt < 6; kt++) {
                    uint2 a02 = *(const uint2*)&sAp[((kt * 16 + g) << 4) + tq4 * 4];
                    uint2 a13 = *(const uint2*)&sAp[((kt * 16 + g + 8) << 4) + tq4 * 4];
                    uint2 bb  = *(const uint2*)&sBBph[((kt * 32 + j) << 4) + tq4 * 4];
                    mma16816(c0, c1, cc2, c3, a02.x, a13.x, a02.y, a13.y, bb.x, bb.y);
                }
            } else {
#pragma unroll
                for (int kt = 2; kt < 6; kt++) {
                    uint2 a02 = *(const uint2*)&sAp[((kt * 16 + g) << 4) + tq4 * 4];
                    uint2 a13 = *(const uint2*)&sAp[((kt * 16 + g + 8) << 4) + tq4 * 4];
                    uint2 bb  = *(const uint2*)&sBBpl[((kt * 32 + j) << 4) + tq4 * 4];
                    mma16816(c0, c1, cc2, c3, a02.x, a13.x, a02.y, a13.y, bb.x, bb.y);
                }
            }
            int jc = ((wid < 4) ? 0 : 32) + 8 * wsub + 2 * tq4;
            *(float2*)&sZT[g][jc]     = make_float2(c0, c1);
            *(float2*)&sZT[g + 8][jc] = make_float2(cc2, c3);
            __syncthreads();

            // epilogue: hn = Z*h + (1-Z)*tanh(hi+lo+bias); stage hn for fc
            float hn[2];
#pragma unroll
            for (int q = 0; q < 2; q++) {
                int it = tid + q * 256;
                int nn = it >> 5, c = it & 31;
                int gn = n0 + nn;
                float ct = sZT[nn][c] + sZT[nn][32 + c] + s_bh[c];
                float z = g_Z[gn * CH + c];
                float h = g_h[gn * CH + c];
                float v = z * h + (1.f - z) * tanhf(ct);
                hn[q] = v;
                g_h[gn * CH + c] = v;
                g_h16[gn * CH + c] = __float2half(v);
            }
            __syncthreads();
#pragma unroll
            for (int q = 0; q < 2; q++) {
                int it = tid + q * 256;
                sZT[it >> 5][it & 31] = hn[q];
            }
            __syncthreads();
            if (tid < 128) {
                int nn = tid >> 3, jj = tid & 7;
                float acc = s_fcb[jj];
#pragma unroll
                for (int c = 0; c < CH; c++) acc += sZT[nn][c] * s_fcw[c * COUTC + jj];
                out[((size_t)t * NN + n0 + nn) * COUTC + jj] = acc;
            }
            __syncthreads();
        }

        // ---- grid barrier (h published for next step) ----
        gen++;
        __syncthreads();
        if (tid == 0) {
            __threadfence();
            if (atomicAdd(&g_cnt, 1) == NB - 1) {
                g_cnt = 0;
                __threadfence();
                g_release = gen;
            } else {
                while (g_release < gen) { }
            }
        }
        __syncthreads();
    }
}

// ---------------- launch ----------------
extern "C" void kernel_launch(void* const* d_in, const int* in_sizes, int n_in,
                              void* d_out, int out_size) {
    const float* X   = (const float*)d_in[0];
    const void*  ei  = d_in[1];
    const float* Wxz = (const float*)d_in[2];
    const float* bxz = (const float*)d_in[3];
    const float* Whz = (const float*)d_in[4];
    const float* bhz = (const float*)d_in[5];
    const float* Wxr = (const float*)d_in[6];
    const float* bxr = (const float*)d_in[7];
    const float* Whr = (const float*)d_in[8];
    const float* bhr = (const float*)d_in[9];
    const float* Wxh = (const float*)d_in[10];
    const float* bxh = (const float*)d_in[11];
    const float* Whh = (const float*)d_in[12];
    const float* bhh = (const float*)d_in[13];
    const float* fcw = (const float*)d_in[14];
    const float* fcb = (const float*)d_in[15];
    float* out = (float*)d_out;

    int E = in_sizes[1] / 2;

    // preprocess: count(0), scan(1), fill(2) -> k_gru is launch idx 3
    k_count<<<(E + 255) / 256, 256>>>(ei, X, E);
    k_scan<<<1, 1024>>>();
    k_fill<<<(E + 255) / 256, 256>>>(ei, E);

    // persistent: AX prologue + all 128 recurrence steps in ONE launch
    k_gru<<<NB, 256>>>(Wxz, bxz, Whz, bhz, Wxr, bxr, Whr, bhr,
                       Wxh, bxh, Whh, bhh, fcw, fcb, out);
}